// round 7
// baseline (speedup 1.0000x reference)
#include <cuda_runtime.h>
#include <cuda_bf16.h>
#include <cstdint>

using bf16 = __nv_bfloat16;

namespace {
constexpr int BATCH=8, NA=1024, ND=4096, C=512, CI=256;
constexpr int RA=BATCH*NA, RD=BATCH*ND;
constexpr float EPS=1e-3f;
constexpr int SPLITK=8;
constexpr int STAGE_B = 24576;           // AH4K|AL4K|BH8K|BL8K
constexpr int SMEM_BYTES = 4*STAGE_B;    // 96KB, 4 stages
}

// ---- bf16 hi/lo split buffers (bss) ----
__device__ __align__(16) bf16 g_detH[(long)RD*C], g_detL[(long)RD*C];
__device__ __align__(16) bf16 g_aimH[(long)RA*C], g_aimL[(long)RA*C];
__device__ __align__(16) bf16 g_WgH[C*CI], g_WgL[C*CI];
__device__ __align__(16) bf16 g_WtH[C*CI], g_WtL[C*CI];
__device__ __align__(16) bf16 g_WpH[C*CI], g_WpL[C*CI];
__device__ __align__(16) bf16 g_WwH[CI*C], g_WwL[CI*C];
__device__ __align__(16) bf16 g_WqH[CI*C], g_WqL[CI*C];
__device__ __align__(16) bf16 g_dxH[(long)RD*CI], g_dxL[(long)RD*CI];
__device__ __align__(16) bf16 g_phH[(long)RD*CI], g_phL[(long)RD*CI];
__device__ __align__(16) bf16 g_axH[(long)RA*CI], g_axL[(long)RA*CI];
__device__ __align__(16) bf16 g_thH[(long)RA*CI], g_thL[(long)RA*CI];
__device__ __align__(16) float g_p1[(long)BATCH*SPLITK*CI*CI];
__device__ __align__(16) float g_p2[(long)BATCH*SPLITK*CI*CI];
__device__ __align__(16) bf16 g_m1H[(long)BATCH*CI*CI], g_m1L[(long)BATCH*CI*CI];
__device__ __align__(16) bf16 g_m2H[(long)BATCH*CI*CI], g_m2L[(long)BATCH*CI*CI];
__device__ __align__(16) bf16 g_napH[(long)RA*CI], g_napL[(long)RA*CI];
__device__ __align__(16) bf16 g_ndpH[(long)RD*CI], g_ndpL[(long)RD*CI];

__device__ __forceinline__ void mma_bf16(float* c, const uint32_t* a, uint32_t b0, uint32_t b1){
    asm volatile("mma.sync.aligned.m16n8k16.row.col.f32.bf16.bf16.f32 "
        "{%0,%1,%2,%3},{%4,%5,%6,%7},{%8,%9},{%0,%1,%2,%3};\n"
        : "+f"(c[0]),"+f"(c[1]),"+f"(c[2]),"+f"(c[3])
        : "r"(a[0]),"r"(a[1]),"r"(a[2]),"r"(a[3]),"r"(b0),"r"(b1));
}
__device__ __forceinline__ void ldsm4(uint32_t* r, uint32_t a){
    asm volatile("ldmatrix.sync.aligned.m8n8.x4.shared.b16 {%0,%1,%2,%3},[%4];"
        : "=r"(r[0]),"=r"(r[1]),"=r"(r[2]),"=r"(r[3]) : "r"(a));
}
__device__ __forceinline__ void ldsm4t(uint32_t* r, uint32_t a){
    asm volatile("ldmatrix.sync.aligned.m8n8.x4.trans.shared.b16 {%0,%1,%2,%3},[%4];"
        : "=r"(r[0]),"=r"(r[1]),"=r"(r[2]),"=r"(r[3]) : "r"(a));
}
__device__ __forceinline__ void cpa16(uint32_t dst, const void* src){
    asm volatile("cp.async.cg.shared.global [%0], [%1], 16;" :: "r"(dst),"l"(src));
}
#define CP_COMMIT() asm volatile("cp.async.commit_group;")
#define CP_WAIT2()  asm volatile("cp.async.wait_group 2;")

// CTA tile 128(M) x 256(N), k-chunk 16, 8 warps (2x4), warp tile 64x64.
// MODE: 0 plain, 1 +bias, 2 *scale, 3 BN(acc+bias)+resid
// TA: A stored (K x M) -> compute A^T @ B.   B always stored (K x N).
// OUTB: write bf16 hi/lo outputs; else fp32.
template<int MODE, bool TA, bool OUTB>
__global__ __launch_bounds__(256, 1)
void gemm_cp(const bf16* __restrict__ AH, const bf16* __restrict__ AL,
             const bf16* __restrict__ BH, const bf16* __restrict__ BL,
             float* __restrict__ Cf, bf16* __restrict__ CH, bf16* __restrict__ CL,
             int K, long lda, long ldb, long ldc,
             long zA, long zB, long zC,
             const float* __restrict__ bias, float scale,
             const float* __restrict__ gam, const float* __restrict__ beta,
             const float* __restrict__ mean, const float* __restrict__ var,
             const float* __restrict__ resid)
{
    extern __shared__ __align__(128) char smem[];
    const int tid=threadIdx.x, lane=tid&31, warp=tid>>5;
    const int z=blockIdx.z;
    AH += (long)z*zA; AL += (long)z*zA;
    BH += (long)z*zB; BL += (long)z*zB;
    const long co = (long)z*zC;
    const int m0 = blockIdx.y*128, n0 = blockIdx.x*256;
    const uint32_t sb = (uint32_t)__cvta_generic_to_shared(smem);

    // ---- cp.async source/dest ----
    const bf16 *pAH, *pAL;
    uint32_t dA; long stepA;
    if (!TA){                              // A (M x K): 128 rows x 2 k8-halves
        const int row=tid>>1, k8=tid&1;
        const long o = (long)(m0+row)*lda + k8*8;
        pAH = AH+o; pAL = AL+o;
        dA = (uint32_t)(row*2 + (k8 ^ ((row>>2)&1)))*16;
        stepA = 16;
    } else {                               // A (K x M): 16 k-rows x 16 m8-chunks
        const int k=tid>>4, m8=tid&15;
        const long o = (long)k*lda + m0 + m8*8;
        pAH = AH+o; pAL = AL+o;
        dA = (uint32_t)(k*16 + (m8 ^ (k&7)))*16;
        stepA = 16*lda;
    }
    const int kb=tid>>5, n8=tid&31;        // B (K x N): 16 k-rows x 32 n8-chunks, 2 rows/thread
    const long oB = (long)kb*ldb + n0 + n8*8;
    const bf16 *pBH = BH+oB, *pBL = BL+oB;
    const uint32_t dB = (uint32_t)(kb*32 + (n8 ^ (kb&7)))*16;  // second row at +4096, src +8*ldb
    const long stepB = 16*ldb;

    // ---- ldsm chunk indices ----
    const int wm0 = (warp>>2)*64, wn0 = (warp&3)*64;
    const int g = lane>>3;
    int aCh[4];
#pragma unroll
    for (int mt=0; mt<4; mt++){
        if (!TA){
            const int row = wm0 + mt*16 + (lane&7) + (g&1)*8;
            aCh[mt] = row*2 + ((g>>1) ^ ((row>>2)&1));
        } else {
            const int row = (lane&7) + (g>>1)*8;
            const int c = ((wm0 + mt*16)>>3) + (g&1);
            aCh[mt] = row*16 + (c ^ (row&7));
        }
    }
    int bCh[4];
#pragma unroll
    for (int np=0; np<4; np++){
        const int row = (lane&7) + (g&1)*8;
        const int c = ((wn0 + np*16)>>3) + (g>>1);
        bCh[np] = row*32 + (c ^ (row&7));
    }

    float acc[4][8][4];
#pragma unroll
    for (int mt=0;mt<4;mt++)
#pragma unroll
        for (int nt=0;nt<8;nt++)
#pragma unroll
            for (int i=0;i<4;i++) acc[mt][nt][i]=0.f;

    const int NC = K>>4;
    // prologue: stages 0..2
#pragma unroll
    for (int c=0; c<3; c++){
        const uint32_t ba = sb + c*STAGE_B;
        cpa16(ba        + dA, pAH + (long)c*stepA);
        cpa16(ba + 4096 + dA, pAL + (long)c*stepA);
        cpa16(ba + 8192         + dB, pBH + (long)c*stepB);
        cpa16(ba + 8192  + 4096 + dB, pBH + (long)c*stepB + 8*ldb);
        cpa16(ba + 16384        + dB, pBL + (long)c*stepB);
        cpa16(ba + 16384 + 4096 + dB, pBL + (long)c*stepB + 8*ldb);
        CP_COMMIT();
    }

#pragma unroll 1
    for (int c=0; c<NC; c++){
        CP_WAIT2();
        __syncthreads();
        if (c+3 < NC){
            const uint32_t ba = sb + ((c+3)&3)*STAGE_B;
            cpa16(ba        + dA, pAH + (long)(c+3)*stepA);
            cpa16(ba + 4096 + dA, pAL + (long)(c+3)*stepA);
            cpa16(ba + 8192         + dB, pBH + (long)(c+3)*stepB);
            cpa16(ba + 8192  + 4096 + dB, pBH + (long)(c+3)*stepB + 8*ldb);
            cpa16(ba + 16384        + dB, pBL + (long)(c+3)*stepB);
            cpa16(ba + 16384 + 4096 + dB, pBL + (long)(c+3)*stepB + 8*ldb);
        }
        CP_COMMIT();

        const uint32_t ba = sb + (c&3)*STAGE_B;
        uint32_t Ah[4][4], Al[4][4], Bh[4][4], Bl[4][4];
#pragma unroll
        for (int mt=0; mt<4; mt++){
            if (!TA){
                ldsm4 (Ah[mt], ba + aCh[mt]*16);
                ldsm4 (Al[mt], ba + 4096 + aCh[mt]*16);
            } else {
                ldsm4t(Ah[mt], ba + aCh[mt]*16);
                ldsm4t(Al[mt], ba + 4096 + aCh[mt]*16);
            }
        }
#pragma unroll
        for (int np=0; np<4; np++){
            ldsm4t(Bh[np], ba + 8192  + bCh[np]*16);
            ldsm4t(Bl[np], ba + 16384 + bCh[np]*16);
        }
        // term hh (32 mma), then hl, then lh: same acc revisited only every 32 mmas
#pragma unroll
        for (int mt=0; mt<4; mt++)
#pragma unroll
            for (int np=0; np<4; np++){
                mma_bf16(acc[mt][np*2],   Ah[mt], Bh[np][0], Bh[np][1]);
                mma_bf16(acc[mt][np*2+1], Ah[mt], Bh[np][2], Bh[np][3]);
            }
#pragma unroll
        for (int mt=0; mt<4; mt++)
#pragma unroll
            for (int np=0; np<4; np++){
                mma_bf16(acc[mt][np*2],   Ah[mt], Bl[np][0], Bl[np][1]);
                mma_bf16(acc[mt][np*2+1], Ah[mt], Bl[np][2], Bl[np][3]);
            }
#pragma unroll
        for (int mt=0; mt<4; mt++)
#pragma unroll
            for (int np=0; np<4; np++){
                mma_bf16(acc[mt][np*2],   Al[mt], Bh[np][0], Bh[np][1]);
                mma_bf16(acc[mt][np*2+1], Al[mt], Bh[np][2], Bh[np][3]);
            }
    }

    // ---- epilogue ----
    const int rbase = m0 + wm0 + (lane>>2);
    const int cbase = n0 + wn0 + (lane&3)*2;
#pragma unroll
    for (int mt=0; mt<4; mt++){
#pragma unroll
        for (int nt=0; nt<8; nt++){
            const int col = cbase + nt*8;
#pragma unroll
            for (int hf=0; hf<2; hf++){
                const int row = rbase + mt*16 + hf*8;
                float v0 = acc[mt][nt][hf*2];
                float v1 = acc[mt][nt][hf*2+1];
                if (MODE==1){ v0 += bias[col]; v1 += bias[col+1]; }
                if (MODE==2){ v0 *= scale;     v1 *= scale; }
                if (MODE==3){
                    const float s0 = gam[col]  *rsqrtf(var[col]  +EPS);
                    const float s1 = gam[col+1]*rsqrtf(var[col+1]+EPS);
                    const float2 rr = *(const float2*)&resid[co + (long)row*ldc + col];
                    v0 = (v0 + bias[col]  - mean[col])  *s0 + beta[col]   + rr.x;
                    v1 = (v1 + bias[col+1]- mean[col+1])*s1 + beta[col+1] + rr.y;
                }
                const long gidx = co + (long)row*ldc + col;
                if (OUTB){
                    const bf16 h0 = __float2bfloat16_rn(v0);
                    const bf16 h1 = __float2bfloat16_rn(v1);
                    const bf16 l0 = __float2bfloat16_rn(v0 - __bfloat162float(h0));
                    const bf16 l1 = __float2bfloat16_rn(v1 - __bfloat162float(h1));
                    __nv_bfloat162 hp = {h0,h1}, lp = {l0,l1};
                    *(uint32_t*)&CH[gidx] = *(uint32_t*)&hp;
                    *(uint32_t*)&CL[gidx] = *(uint32_t*)&lp;
                } else {
                    *(float2*)&Cf[gidx] = make_float2(v0, v1);
                }
            }
        }
    }
}

__global__ __launch_bounds__(256) void fsplit(const float* __restrict__ x,
                                              bf16* __restrict__ h, bf16* __restrict__ l, int n4){
    const int i = blockIdx.x*256 + threadIdx.x;
    if (i >= n4) return;
    const float4 v = ((const float4*)x)[i];
    const float f[4] = {v.x,v.y,v.z,v.w};
    bf16 hh[4], ll[4];
#pragma unroll
    for (int j=0;j<4;j++){
        hh[j] = __float2bfloat16_rn(f[j]);
        ll[j] = __float2bfloat16_rn(f[j] - __bfloat162float(hh[j]));
    }
    ((uint2*)h)[i] = *(uint2*)hh;
    ((uint2*)l)[i] = *(uint2*)ll;
}

__global__ void reduce8b(const float* __restrict__ part, bf16* __restrict__ oh, bf16* __restrict__ ol){
    const int nper = CI*CI;
    const int i = blockIdx.x*blockDim.x + threadIdx.x;
    if (i >= BATCH*nper) return;
    const int b = i/nper, r = i - b*nper;
    const float* p = part + (long)b*SPLITK*nper + r;
    float s = 0.f;
#pragma unroll
    for (int k=0;k<SPLITK;k++) s += p[(long)k*nper];
    const bf16 h = __float2bfloat16_rn(s);
    oh[i] = h;
    ol[i] = __float2bfloat16_rn(s - __bfloat162float(h));
}

#define SYM(p, s) cudaGetSymbolAddress((void**)&p, s)

extern "C" void kernel_launch(void* const* d_in, const int* in_sizes, int n_in,
                              void* d_out, int out_size){
    (void)in_sizes; (void)n_in; (void)out_size;
    const float* detect=(const float*)d_in[0];
    const float* aim   =(const float*)d_in[1];
    const float* Wg=(const float*)d_in[2];  const float* bg=(const float*)d_in[3];
    const float* Wt=(const float*)d_in[4];  const float* bt=(const float*)d_in[5];
    const float* Wp=(const float*)d_in[6];  const float* bp=(const float*)d_in[7];
    const float* Ww=(const float*)d_in[8];  const float* bw=(const float*)d_in[9];
    const float* gw=(const float*)d_in[10]; const float* betw=(const float*)d_in[11];
    const float* mw=(const float*)d_in[12]; const float* vw=(const float*)d_in[13];
    const float* Wq=(const float*)d_in[14]; const float* bq=(const float*)d_in[15];
    const float* gq=(const float*)d_in[16]; const float* betq=(const float*)d_in[17];
    const float* mq=(const float*)d_in[18]; const float* vq=(const float*)d_in[19];

    float* out    = (float*)d_out;
    float* out_na = out;
    float* out_nd = out + (long)RA*C;

    bf16 *detH,*detL,*aimH,*aimL,*WgH,*WgL,*WtH,*WtL,*WpH,*WpL,*WwH,*WwL,*WqH,*WqL;
    bf16 *dxH,*dxL,*phH,*phL,*axH,*axL,*thH,*thL,*m1H,*m1L,*m2H,*m2L,*napH,*napL,*ndpH,*ndpL;
    float *p1,*p2;
    SYM(detH,g_detH); SYM(detL,g_detL); SYM(aimH,g_aimH); SYM(aimL,g_aimL);
    SYM(WgH,g_WgH); SYM(WgL,g_WgL); SYM(WtH,g_WtH); SYM(WtL,g_WtL);
    SYM(WpH,g_WpH); SYM(WpL,g_WpL); SYM(WwH,g_WwH); SYM(WwL,g_WwL);
    SYM(WqH,g_WqH); SYM(WqL,g_WqL);
    SYM(dxH,g_dxH); SYM(dxL,g_dxL); SYM(phH,g_phH); SYM(phL,g_phL);
    SYM(axH,g_axH); SYM(axL,g_axL); SYM(thH,g_thH); SYM(thL,g_thL);
    SYM(m1H,g_m1H); SYM(m1L,g_m1L); SYM(m2H,g_m2H); SYM(m2L,g_m2L);
    SYM(napH,g_napH); SYM(napL,g_napL); SYM(ndpH,g_ndpH); SYM(ndpL,g_ndpL);
    SYM(p1,g_p1); SYM(p2,g_p2);

    cudaFuncSetAttribute(gemm_cp<1,false,true >, cudaFuncAttributeMaxDynamicSharedMemorySize, SMEM_BYTES);
    cudaFuncSetAttribute(gemm_cp<2,true ,false>, cudaFuncAttributeMaxDynamicSharedMemorySize, SMEM_BYTES);
    cudaFuncSetAttribute(gemm_cp<0,false,true >, cudaFuncAttributeMaxDynamicSharedMemorySize, SMEM_BYTES);
    cudaFuncSetAttribute(gemm_cp<3,false,false>, cudaFuncAttributeMaxDynamicSharedMemorySize, SMEM_BYTES);

    const dim3 blk(256);

    // prepass splits
    fsplit<<<(RD*C/4+255)/256, 256>>>(detect, detH, detL, RD*C/4);
    fsplit<<<(RA*C/4+255)/256, 256>>>(aim,    aimH, aimL, RA*C/4);
    fsplit<<<(C*CI/4+255)/256, 256>>>(Wg, WgH, WgL, C*CI/4);
    fsplit<<<(C*CI/4+255)/256, 256>>>(Wt, WtH, WtL, C*CI/4);
    fsplit<<<(C*CI/4+255)/256, 256>>>(Wp, WpH, WpL, C*CI/4);
    fsplit<<<(CI*C/4+255)/256, 256>>>(Ww, WwH, WwL, CI*C/4);
    fsplit<<<(CI*C/4+255)/256, 256>>>(Wq, WqH, WqL, CI*C/4);

    const long sM = (long)CI*CI;

    // projections: X @ W + b -> bf16 pairs   (grid: N/256 x M/128)
    gemm_cp<1,false,true><<<dim3(1,RD/128,1),blk,SMEM_BYTES>>>(detH,detL,WgH,WgL,
        nullptr,dxH,dxL, C, C,CI,CI, 0,0,0, bg,0.f,nullptr,nullptr,nullptr,nullptr,nullptr);
    gemm_cp<1,false,true><<<dim3(1,RD/128,1),blk,SMEM_BYTES>>>(detH,detL,WpH,WpL,
        nullptr,phH,phL, C, C,CI,CI, 0,0,0, bp,0.f,nullptr,nullptr,nullptr,nullptr,nullptr);
    gemm_cp<1,false,true><<<dim3(1,RA/128,1),blk,SMEM_BYTES>>>(aimH,aimL,WgH,WgL,
        nullptr,axH,axL, C, C,CI,CI, 0,0,0, bg,0.f,nullptr,nullptr,nullptr,nullptr,nullptr);
    gemm_cp<1,false,true><<<dim3(1,RA/128,1),blk,SMEM_BYTES>>>(aimH,aimL,WtH,WtL,
        nullptr,thH,thL, C, C,CI,CI, 0,0,0, bt,0.f,nullptr,nullptr,nullptr,nullptr,nullptr);

    // gram: m1 = ph^T dx / ND ; m2 = th^T ax / NA  (split-K x8, fp32 partials)
    gemm_cp<2,true,false><<<dim3(1,2,BATCH*SPLITK),blk,SMEM_BYTES>>>(phH,phL,dxH,dxL,
        p1,nullptr,nullptr, ND/SPLITK, CI,CI,CI,
        (long)(ND/SPLITK)*CI,(long)(ND/SPLITK)*CI,sM,
        nullptr,1.f/(float)ND,nullptr,nullptr,nullptr,nullptr,nullptr);
    gemm_cp<2,true,false><<<dim3(1,2,BATCH*SPLITK),blk,SMEM_BYTES>>>(thH,thL,axH,axL,
        p2,nullptr,nullptr, NA/SPLITK, CI,CI,CI,
        (long)(NA/SPLITK)*CI,(long)(NA/SPLITK)*CI,sM,
        nullptr,1.f/(float)NA,nullptr,nullptr,nullptr,nullptr,nullptr);
    {
        const int n = BATCH*CI*CI;
        reduce8b<<<(n+255)/256,256>>>(p1, m1H, m1L);
        reduce8b<<<(n+255)/256,256>>>(p2, m2H, m2L);
    }

    // apply: nap = th @ m1 ; ndp = ph @ m2 -> bf16 pairs
    gemm_cp<0,false,true><<<dim3(1,NA/128,BATCH),blk,SMEM_BYTES>>>(thH,thL,m1H,m1L,
        nullptr,napH,napL, CI, CI,CI,CI, (long)NA*CI,sM,(long)NA*CI,
        nullptr,0.f,nullptr,nullptr,nullptr,nullptr,nullptr);
    gemm_cp<0,false,true><<<dim3(1,ND/128,BATCH),blk,SMEM_BYTES>>>(phH,phL,m2H,m2L,
        nullptr,ndpH,ndpL, CI, CI,CI,CI, (long)ND*CI,sM,(long)ND*CI,
        nullptr,0.f,nullptr,nullptr,nullptr,nullptr,nullptr);

    // output convs: BN + residual, fp32 out
    gemm_cp<3,false,false><<<dim3(2,RA/128,1),blk,SMEM_BYTES>>>(napH,napL,WwH,WwL,
        out_na,nullptr,nullptr, CI, CI,C,C, 0,0,0,
        bw,0.f,gw,betw,mw,vw,aim);
    gemm_cp<3,false,false><<<dim3(2,RD/128,1),blk,SMEM_BYTES>>>(ndpH,ndpL,WqH,WqL,
        out_nd,nullptr,nullptr, CI, CI,C,C, 0,0,0,
        bq,0.f,gq,betq,mq,vq,detect);
}

// round 8
// speedup vs baseline: 1.1391x; 1.1391x over previous
#include <cuda_runtime.h>
#include <cuda_bf16.h>
#include <cstdint>

using bf16 = __nv_bfloat16;

namespace {
constexpr int BATCH=8, NA=1024, ND=4096, C=512, CI=256;
constexpr int RA=BATCH*NA, RD=BATCH*ND;
constexpr float EPS=1e-3f;
constexpr int SPLITK=8;
constexpr int STAGE_B = 32768;           // k32 stage: AH8K|AL8K|BH8K|BL8K
constexpr int SMEM_BYTES = 3*STAGE_B;    // 96KB, 3 stages
}

// ---- bf16 hi/lo split buffers (bss) ----
__device__ __align__(16) bf16 g_detH[(long)RD*C], g_detL[(long)RD*C];
__device__ __align__(16) bf16 g_aimH[(long)RA*C], g_aimL[(long)RA*C];
__device__ __align__(16) bf16 g_WgH[C*CI], g_WgL[C*CI];
__device__ __align__(16) bf16 g_WtH[C*CI], g_WtL[C*CI];
__device__ __align__(16) bf16 g_WpH[C*CI], g_WpL[C*CI];
__device__ __align__(16) bf16 g_WwH[CI*C], g_WwL[CI*C];
__device__ __align__(16) bf16 g_WqH[CI*C], g_WqL[CI*C];
__device__ __align__(16) bf16 g_dxH[(long)RD*CI], g_dxL[(long)RD*CI];
__device__ __align__(16) bf16 g_phH[(long)RD*CI], g_phL[(long)RD*CI];
__device__ __align__(16) bf16 g_axH[(long)RA*CI], g_axL[(long)RA*CI];
__device__ __align__(16) bf16 g_thH[(long)RA*CI], g_thL[(long)RA*CI];
__device__ __align__(16) float g_p1[(long)BATCH*SPLITK*CI*CI];
__device__ __align__(16) float g_p2[(long)BATCH*SPLITK*CI*CI];
__device__ __align__(16) bf16 g_m1H[(long)BATCH*CI*CI], g_m1L[(long)BATCH*CI*CI];
__device__ __align__(16) bf16 g_m2H[(long)BATCH*CI*CI], g_m2L[(long)BATCH*CI*CI];
__device__ __align__(16) bf16 g_napH[(long)RA*CI], g_napL[(long)RA*CI];
__device__ __align__(16) bf16 g_ndpH[(long)RD*CI], g_ndpL[(long)RD*CI];

__device__ __forceinline__ void mma_bf16(float* c, const uint32_t* a, uint32_t b0, uint32_t b1){
    asm volatile("mma.sync.aligned.m16n8k16.row.col.f32.bf16.bf16.f32 "
        "{%0,%1,%2,%3},{%4,%5,%6,%7},{%8,%9},{%0,%1,%2,%3};\n"
        : "+f"(c[0]),"+f"(c[1]),"+f"(c[2]),"+f"(c[3])
        : "r"(a[0]),"r"(a[1]),"r"(a[2]),"r"(a[3]),"r"(b0),"r"(b1));
}
__device__ __forceinline__ void ldsm4(uint32_t* r, uint32_t a){
    asm volatile("ldmatrix.sync.aligned.m8n8.x4.shared.b16 {%0,%1,%2,%3},[%4];"
        : "=r"(r[0]),"=r"(r[1]),"=r"(r[2]),"=r"(r[3]) : "r"(a));
}
__device__ __forceinline__ void ldsm4t(uint32_t* r, uint32_t a){
    asm volatile("ldmatrix.sync.aligned.m8n8.x4.trans.shared.b16 {%0,%1,%2,%3},[%4];"
        : "=r"(r[0]),"=r"(r[1]),"=r"(r[2]),"=r"(r[3]) : "r"(a));
}
__device__ __forceinline__ void cpa16(uint32_t dst, const void* src){
    asm volatile("cp.async.cg.shared.global [%0], [%1], 16;" :: "r"(dst),"l"(src));
}
#define CP_COMMIT() asm volatile("cp.async.commit_group;")
#define CP_WAIT1()  asm volatile("cp.async.wait_group 1;")

// CTA tile 128x128, k-stage 32 (two k16 halves), 8 warps (4x2), warp tile 32x64.
// MODE: 0 plain, 1 +bias, 2 *scale, 3 BN(acc+bias)+resid
// TA: A stored (K x M) -> compute A^T @ B.   B always stored (K x N).
// OUTB: write bf16 hi/lo outputs; else fp32.
template<int MODE, bool TA, bool OUTB>
__global__ __launch_bounds__(256, 2)
void gemm_cp(const bf16* __restrict__ AH, const bf16* __restrict__ AL,
             const bf16* __restrict__ BH, const bf16* __restrict__ BL,
             float* __restrict__ Cf, bf16* __restrict__ CH, bf16* __restrict__ CL,
             int K, long lda, long ldb, long ldc,
             long zA, long zB, long zC,
             const float* __restrict__ bias, float scale,
             const float* __restrict__ gam, const float* __restrict__ beta,
             const float* __restrict__ mean, const float* __restrict__ var,
             const float* __restrict__ resid)
{
    extern __shared__ __align__(128) char smem[];
    const int tid=threadIdx.x, lane=tid&31, warp=tid>>5;
    const int z=blockIdx.z;
    AH += (long)z*zA; AL += (long)z*zA;
    BH += (long)z*zB; BL += (long)z*zB;
    const long co = (long)z*zC;
    const int m0 = blockIdx.y*128, n0 = blockIdx.x*128;
    const uint32_t sb = (uint32_t)__cvta_generic_to_shared(smem);

    // ---- per-thread cp.async element coords (2 elems per operand per stage) ----
    // A: idx = i*256+tid over 512 slots
    int aRow[2], aK8[2];     // !TA: row 0..127, k8 0..3   ; TA: k 0..31, m8 0..15
    uint32_t dA[2];          // dst offset within stage (AH region)
#pragma unroll
    for (int i=0;i<2;i++){
        const int idx = i*256 + tid;
        if (!TA){
            const int row = idx>>2, k8 = idx&3;
            const int half = k8>>1, kk = k8&1;
            aRow[i]=row; aK8[i]=k8;
            dA[i] = half*4096 + (uint32_t)(row*2 + (kk ^ ((row>>2)&1)))*16;
        } else {
            const int k = idx>>4, m8 = idx&15;
            const int half = k>>4, kr = k&15;
            aRow[i]=k; aK8[i]=m8;
            dA[i] = half*4096 + (uint32_t)(kr*16 + (m8 ^ (kr&7)))*16;
        }
    }
    int bK[2], bN8[2]; uint32_t dB[2];
#pragma unroll
    for (int i=0;i<2;i++){
        const int idx = i*256 + tid;
        const int k = idx>>4, n8 = idx&15;
        const int half = k>>4, kr = k&15;
        bK[i]=k; bN8[i]=n8;
        dB[i] = half*4096 + (uint32_t)(kr*16 + (n8 ^ (kr&7)))*16;
    }

    // ---- ldsm chunk indices (within a 4KB k16-half block) ----
    const int wm0 = (warp>>1)*32, wn0 = (warp&1)*64;
    const int g = lane>>3;
    int aCh[2];
#pragma unroll
    for (int mt=0; mt<2; mt++){
        if (!TA){
            const int row = wm0 + mt*16 + (lane&7) + (g&1)*8;
            aCh[mt] = row*2 + ((g>>1) ^ ((row>>2)&1));
        } else {
            const int row = (lane&7) + (g>>1)*8;
            const int c = ((wm0 + mt*16)>>3) + (g&1);
            aCh[mt] = row*16 + (c ^ (row&7));
        }
    }
    int bCh[4];
#pragma unroll
    for (int np=0; np<4; np++){
        const int row = (lane&7) + (g&1)*8;
        const int c = ((wn0 + np*16)>>3) + (g>>1);
        bCh[np] = row*16 + (c ^ (row&7));
    }

    float acc[2][8][4];
#pragma unroll
    for (int mt=0;mt<2;mt++)
#pragma unroll
        for (int nt=0;nt<8;nt++)
#pragma unroll
            for (int i=0;i<4;i++) acc[mt][nt][i]=0.f;

    const int NS = K>>5;   // k32 stages

    // stage fill helper (manually inlined twice)
#define FILL_STAGE(S, K0)                                                        \
    {                                                                            \
        const uint32_t ba = sb + (S)*STAGE_B;                                    \
        _Pragma("unroll")                                                        \
        for (int i=0;i<2;i++){                                                   \
            long sa;                                                             \
            if (!TA) sa = (long)(m0 + aRow[i])*lda + (K0) + aK8[i]*8;            \
            else     sa = (long)((K0) + aRow[i])*lda + m0 + aK8[i]*8;            \
            cpa16(ba        + dA[i], AH + sa);                                   \
            cpa16(ba + 8192 + dA[i], AL + sa);                                   \
            const long sbr = (long)((K0) + bK[i])*ldb + n0 + bN8[i]*8;           \
            cpa16(ba + 16384 + dB[i], BH + sbr);                                 \
            cpa16(ba + 24576 + dB[i], BL + sbr);                                 \
        }                                                                        \
    }

    FILL_STAGE(0, 0); CP_COMMIT();
    FILL_STAGE(1, 32); CP_COMMIT();

    int sidx = 0;
#pragma unroll 1
    for (int c=0; c<NS; c++){
        CP_WAIT1();
        __syncthreads();
        if (c+2 < NS){
            const int s2 = (sidx+2 >= 3) ? sidx-1 : sidx+2;
            FILL_STAGE(s2, (c+2)*32);
        }
        CP_COMMIT();

        const uint32_t base = sb + sidx*STAGE_B;
#pragma unroll
        for (int hf=0; hf<2; hf++){
            const uint32_t ha = base + hf*4096;
            uint32_t Ah[2][4], Al[2][4];
#pragma unroll
            for (int mt=0; mt<2; mt++){
                if (!TA){
                    ldsm4 (Ah[mt], ha + aCh[mt]*16);
                    ldsm4 (Al[mt], ha + 8192 + aCh[mt]*16);
                } else {
                    ldsm4t(Ah[mt], ha + aCh[mt]*16);
                    ldsm4t(Al[mt], ha + 8192 + aCh[mt]*16);
                }
            }
#pragma unroll
            for (int np=0; np<4; np++){
                uint32_t Bh[4], Bl[4];
                ldsm4t(Bh, ha + 16384 + bCh[np]*16);
                ldsm4t(Bl, ha + 24576 + bCh[np]*16);
                const int n2 = np*2;
#pragma unroll
                for (int mt=0; mt<2; mt++){
                    mma_bf16(acc[mt][n2],   Ah[mt], Bh[0], Bh[1]);
                    mma_bf16(acc[mt][n2+1], Ah[mt], Bh[2], Bh[3]);
                    mma_bf16(acc[mt][n2],   Ah[mt], Bl[0], Bl[1]);
                    mma_bf16(acc[mt][n2+1], Ah[mt], Bl[2], Bl[3]);
                    mma_bf16(acc[mt][n2],   Al[mt], Bh[0], Bh[1]);
                    mma_bf16(acc[mt][n2+1], Al[mt], Bh[2], Bh[3]);
                }
            }
        }
        sidx = (sidx+1 >= 3) ? 0 : sidx+1;
    }
#undef FILL_STAGE

    // ---- epilogue ----
    const int rbase = m0 + wm0 + (lane>>2);
    const int cbase = n0 + wn0 + (lane&3)*2;
#pragma unroll
    for (int mt=0; mt<2; mt++){
#pragma unroll
        for (int nt=0; nt<8; nt++){
            const int col = cbase + nt*8;
#pragma unroll
            for (int hf=0; hf<2; hf++){
                const int row = rbase + mt*16 + hf*8;
                float v0 = acc[mt][nt][hf*2];
                float v1 = acc[mt][nt][hf*2+1];
                if (MODE==1){ v0 += bias[col]; v1 += bias[col+1]; }
                if (MODE==2){ v0 *= scale;     v1 *= scale; }
                if (MODE==3){
                    const float s0 = gam[col]  *rsqrtf(var[col]  +EPS);
                    const float s1 = gam[col+1]*rsqrtf(var[col+1]+EPS);
                    const float2 rr = *(const float2*)&resid[co + (long)row*ldc + col];
                    v0 = (v0 + bias[col]  - mean[col])  *s0 + beta[col]   + rr.x;
                    v1 = (v1 + bias[col+1]- mean[col+1])*s1 + beta[col+1] + rr.y;
                }
                const long gidx = co + (long)row*ldc + col;
                if (OUTB){
                    const bf16 h0 = __float2bfloat16_rn(v0);
                    const bf16 h1 = __float2bfloat16_rn(v1);
                    const bf16 l0 = __float2bfloat16_rn(v0 - __bfloat162float(h0));
                    const bf16 l1 = __float2bfloat16_rn(v1 - __bfloat162float(h1));
                    __nv_bfloat162 hp = {h0,h1}, lp = {l0,l1};
                    *(uint32_t*)&CH[gidx] = *(uint32_t*)&hp;
                    *(uint32_t*)&CL[gidx] = *(uint32_t*)&lp;
                } else {
                    *(float2*)&Cf[gidx] = make_float2(v0, v1);
                }
            }
        }
    }
}

__global__ __launch_bounds__(256) void fsplit(const float* __restrict__ x,
                                              bf16* __restrict__ h, bf16* __restrict__ l, int n4){
    const int i = blockIdx.x*256 + threadIdx.x;
    if (i >= n4) return;
    const float4 v = ((const float4*)x)[i];
    const float f[4] = {v.x,v.y,v.z,v.w};
    bf16 hh[4], ll[4];
#pragma unroll
    for (int j=0;j<4;j++){
        hh[j] = __float2bfloat16_rn(f[j]);
        ll[j] = __float2bfloat16_rn(f[j] - __bfloat162float(hh[j]));
    }
    ((uint2*)h)[i] = *(uint2*)hh;
    ((uint2*)l)[i] = *(uint2*)ll;
}

__global__ void reduce8b(const float* __restrict__ part, bf16* __restrict__ oh, bf16* __restrict__ ol){
    const int nper = CI*CI;
    const int i = blockIdx.x*blockDim.x + threadIdx.x;
    if (i >= BATCH*nper) return;
    const int b = i/nper, r = i - b*nper;
    const float* p = part + (long)b*SPLITK*nper + r;
    float s = 0.f;
#pragma unroll
    for (int k=0;k<SPLITK;k++) s += p[(long)k*nper];
    const bf16 h = __float2bfloat16_rn(s);
    oh[i] = h;
    ol[i] = __float2bfloat16_rn(s - __bfloat162float(h));
}

#define SYM(p, s) cudaGetSymbolAddress((void**)&p, s)

extern "C" void kernel_launch(void* const* d_in, const int* in_sizes, int n_in,
                              void* d_out, int out_size){
    (void)in_sizes; (void)n_in; (void)out_size;
    const float* detect=(const float*)d_in[0];
    const float* aim   =(const float*)d_in[1];
    const float* Wg=(const float*)d_in[2];  const float* bg=(const float*)d_in[3];
    const float* Wt=(const float*)d_in[4];  const float* bt=(const float*)d_in[5];
    const float* Wp=(const float*)d_in[6];  const float* bp=(const float*)d_in[7];
    const float* Ww=(const float*)d_in[8];  const float* bw=(const float*)d_in[9];
    const float* gw=(const float*)d_in[10]; const float* betw=(const float*)d_in[11];
    const float* mw=(const float*)d_in[12]; const float* vw=(const float*)d_in[13];
    const float* Wq=(const float*)d_in[14]; const float* bq=(const float*)d_in[15];
    const float* gq=(const float*)d_in[16]; const float* betq=(const float*)d_in[17];
    const float* mq=(const float*)d_in[18]; const float* vq=(const float*)d_in[19];

    float* out    = (float*)d_out;
    float* out_na = out;
    float* out_nd = out + (long)RA*C;

    bf16 *detH,*detL,*aimH,*aimL,*WgH,*WgL,*WtH,*WtL,*WpH,*WpL,*WwH,*WwL,*WqH,*WqL;
    bf16 *dxH,*dxL,*phH,*phL,*axH,*axL,*thH,*thL,*m1H,*m1L,*m2H,*m2L,*napH,*napL,*ndpH,*ndpL;
    float *p1,*p2;
    SYM(detH,g_detH); SYM(detL,g_detL); SYM(aimH,g_aimH); SYM(aimL,g_aimL);
    SYM(WgH,g_WgH); SYM(WgL,g_WgL); SYM(WtH,g_WtH); SYM(WtL,g_WtL);
    SYM(WpH,g_WpH); SYM(WpL,g_WpL); SYM(WwH,g_WwH); SYM(WwL,g_WwL);
    SYM(WqH,g_WqH); SYM(WqL,g_WqL);
    SYM(dxH,g_dxH); SYM(dxL,g_dxL); SYM(phH,g_phH); SYM(phL,g_phL);
    SYM(axH,g_axH); SYM(axL,g_axL); SYM(thH,g_thH); SYM(thL,g_thL);
    SYM(m1H,g_m1H); SYM(m1L,g_m1L); SYM(m2H,g_m2H); SYM(m2L,g_m2L);
    SYM(napH,g_napH); SYM(napL,g_napL); SYM(ndpH,g_ndpH); SYM(ndpL,g_ndpL);
    SYM(p1,g_p1); SYM(p2,g_p2);

    cudaFuncSetAttribute(gemm_cp<1,false,true >, cudaFuncAttributeMaxDynamicSharedMemorySize, SMEM_BYTES);
    cudaFuncSetAttribute(gemm_cp<2,true ,false>, cudaFuncAttributeMaxDynamicSharedMemorySize, SMEM_BYTES);
    cudaFuncSetAttribute(gemm_cp<0,false,true >, cudaFuncAttributeMaxDynamicSharedMemorySize, SMEM_BYTES);
    cudaFuncSetAttribute(gemm_cp<3,false,false>, cudaFuncAttributeMaxDynamicSharedMemorySize, SMEM_BYTES);

    const dim3 blk(256);
    const long sM = (long)CI*CI;

    // prepass splits needed by projections (5 launches), so ncu -s 5 captures
    // the FIRST HEAVY GEMM as launch #6.
    fsplit<<<(RD*C/4+255)/256, 256>>>(detect, detH, detL, RD*C/4);
    fsplit<<<(RA*C/4+255)/256, 256>>>(aim,    aimH, aimL, RA*C/4);
    fsplit<<<(C*CI/4+255)/256, 256>>>(Wg, WgH, WgL, C*CI/4);
    fsplit<<<(C*CI/4+255)/256, 256>>>(Wt, WtH, WtL, C*CI/4);
    fsplit<<<(C*CI/4+255)/256, 256>>>(Wp, WpH, WpL, C*CI/4);

    // projections: X @ W + b -> bf16 pairs
    gemm_cp<1,false,true><<<dim3(2,RD/128,1),blk,SMEM_BYTES>>>(detH,detL,WgH,WgL,
        nullptr,dxH,dxL, C, C,CI,CI, 0,0,0, bg,0.f,nullptr,nullptr,nullptr,nullptr,nullptr);
    gemm_cp<1,false,true><<<dim3(2,RD/128,1),blk,SMEM_BYTES>>>(detH,detL,WpH,WpL,
        nullptr,phH,phL, C, C,CI,CI, 0,0,0, bp,0.f,nullptr,nullptr,nullptr,nullptr,nullptr);
    gemm_cp<1,false,true><<<dim3(2,RA/128,1),blk,SMEM_BYTES>>>(aimH,aimL,WgH,WgL,
        nullptr,axH,axL, C, C,CI,CI, 0,0,0, bg,0.f,nullptr,nullptr,nullptr,nullptr,nullptr);
    gemm_cp<1,false,true><<<dim3(2,RA/128,1),blk,SMEM_BYTES>>>(aimH,aimL,WtH,WtL,
        nullptr,thH,thL, C, C,CI,CI, 0,0,0, bt,0.f,nullptr,nullptr,nullptr,nullptr,nullptr);

    // remaining weight splits
    fsplit<<<(CI*C/4+255)/256, 256>>>(Ww, WwH, WwL, CI*C/4);
    fsplit<<<(CI*C/4+255)/256, 256>>>(Wq, WqH, WqL, CI*C/4);

    // gram: m1 = ph^T dx / ND ; m2 = th^T ax / NA  (split-K x8, fp32 partials)
    gemm_cp<2,true,false><<<dim3(2,2,BATCH*SPLITK),blk,SMEM_BYTES>>>(phH,phL,dxH,dxL,
        p1,nullptr,nullptr, ND/SPLITK, CI,CI,CI,
        (long)(ND/SPLITK)*CI,(long)(ND/SPLITK)*CI,sM,
        nullptr,1.f/(float)ND,nullptr,nullptr,nullptr,nullptr,nullptr);
    gemm_cp<2,true,false><<<dim3(2,2,BATCH*SPLITK),blk,SMEM_BYTES>>>(thH,thL,axH,axL,
        p2,nullptr,nullptr, NA/SPLITK, CI,CI,CI,
        (long)(NA/SPLITK)*CI,(long)(NA/SPLITK)*CI,sM,
        nullptr,1.f/(float)NA,nullptr,nullptr,nullptr,nullptr,nullptr);
    {
        const int n = BATCH*CI*CI;
        reduce8b<<<(n+255)/256,256>>>(p1, m1H, m1L);
        reduce8b<<<(n+255)/256,256>>>(p2, m2H, m2L);
    }

    // apply: nap = th @ m1 ; ndp = ph @ m2 -> bf16 pairs
    gemm_cp<0,false,true><<<dim3(2,NA/128,BATCH),blk,SMEM_BYTES>>>(thH,thL,m1H,m1L,
        nullptr,napH,napL, CI, CI,CI,CI, (long)NA*CI,sM,(long)NA*CI,
        nullptr,0.f,nullptr,nullptr,nullptr,nullptr,nullptr);
    gemm_cp<0,false,true><<<dim3(2,ND/128,BATCH),blk,SMEM_BYTES>>>(phH,phL,m2H,m2L,
        nullptr,ndpH,ndpL, CI, CI,CI,CI, (long)ND*CI,sM,(long)ND*CI,
        nullptr,0.f,nullptr,nullptr,nullptr,nullptr,nullptr);

    // output convs: BN + residual, fp32 out
    gemm_cp<3,false,false><<<dim3(4,RA/128,1),blk,SMEM_BYTES>>>(napH,napL,WwH,WwL,
        out_na,nullptr,nullptr, CI, CI,C,C, 0,0,0,
        bw,0.f,gw,betw,mw,vw,aim);
    gemm_cp<3,false,false><<<dim3(4,RD/128,1),blk,SMEM_BYTES>>>(ndpH,ndpL,WqH,WqL,
        out_nd,nullptr,nullptr, CI, CI,C,C, 0,0,0,
        bq,0.f,gq,betq,mq,vq,detect);
}

// round 9
// speedup vs baseline: 1.3859x; 1.2166x over previous
#include <cuda_runtime.h>
#include <cuda_bf16.h>
#include <cstdint>

using bf16 = __nv_bfloat16;

namespace {
constexpr int BATCH=8, NA=1024, ND=4096, C=512, CI=256;
constexpr int RA=BATCH*NA, RD=BATCH*ND;
constexpr float EPS=1e-3f;
constexpr int SPLITK=8;
constexpr int STAGE_B = 16384;           // k16 stage: AH4K|AL4K|BH4K|BL4K
constexpr int SMEM_BYTES = 4*STAGE_B;    // 64KB, 4 stages
}

// ---- bf16 hi/lo split buffers (bss) ----
__device__ __align__(16) bf16 g_detH[(long)RD*C], g_detL[(long)RD*C];
__device__ __align__(16) bf16 g_aimH[(long)RA*C], g_aimL[(long)RA*C];
__device__ __align__(16) bf16 g_WgH[C*CI], g_WgL[C*CI];
__device__ __align__(16) bf16 g_WtH[C*CI], g_WtL[C*CI];
__device__ __align__(16) bf16 g_WpH[C*CI], g_WpL[C*CI];
__device__ __align__(16) bf16 g_WwH[CI*C], g_WwL[CI*C];
__device__ __align__(16) bf16 g_WqH[CI*C], g_WqL[CI*C];
__device__ __align__(16) bf16 g_dpH[(long)RD*512], g_dpL[(long)RD*512];   // [dx | ph]
__device__ __align__(16) bf16 g_atH[(long)RA*512], g_atL[(long)RA*512];   // [ax | th]
__device__ __align__(16) float g_p1[(long)BATCH*SPLITK*CI*CI];
__device__ __align__(16) float g_p2[(long)BATCH*SPLITK*CI*CI];
__device__ __align__(16) bf16 g_m1H[(long)BATCH*CI*CI], g_m1L[(long)BATCH*CI*CI];
__device__ __align__(16) bf16 g_m2H[(long)BATCH*CI*CI], g_m2L[(long)BATCH*CI*CI];
__device__ __align__(16) bf16 g_m1sH[(long)BATCH*CI*C], g_m1sL[(long)BATCH*CI*C];
__device__ __align__(16) bf16 g_m2sH[(long)BATCH*CI*C], g_m2sL[(long)BATCH*CI*C];
__device__ float g_svw[C], g_bvw[C], g_svq[C], g_bvq[C];

__device__ __forceinline__ void mma_bf16(float* c, const uint32_t* a, uint32_t b0, uint32_t b1){
    asm volatile("mma.sync.aligned.m16n8k16.row.col.f32.bf16.bf16.f32 "
        "{%0,%1,%2,%3},{%4,%5,%6,%7},{%8,%9},{%0,%1,%2,%3};\n"
        : "+f"(c[0]),"+f"(c[1]),"+f"(c[2]),"+f"(c[3])
        : "r"(a[0]),"r"(a[1]),"r"(a[2]),"r"(a[3]),"r"(b0),"r"(b1));
}
__device__ __forceinline__ void ldsm4(uint32_t* r, uint32_t a){
    asm volatile("ldmatrix.sync.aligned.m8n8.x4.shared.b16 {%0,%1,%2,%3},[%4];"
        : "=r"(r[0]),"=r"(r[1]),"=r"(r[2]),"=r"(r[3]) : "r"(a));
}
__device__ __forceinline__ void ldsm4t(uint32_t* r, uint32_t a){
    asm volatile("ldmatrix.sync.aligned.m8n8.x4.trans.shared.b16 {%0,%1,%2,%3},[%4];"
        : "=r"(r[0]),"=r"(r[1]),"=r"(r[2]),"=r"(r[3]) : "r"(a));
}
__device__ __forceinline__ void cpa16(uint32_t dst, const void* src){
    asm volatile("cp.async.cg.shared.global [%0], [%1], 16;" :: "r"(dst),"l"(src));
}
#define CP_COMMIT() asm volatile("cp.async.commit_group;")
#define CP_WAIT2()  asm volatile("cp.async.wait_group 2;")

// CTA tile 128x128, k-chunk 16, 4 stages, 8 warps (4x2), warp tile 32x64.
// MODE: 1 +bias[col-local] (dual-aware), 2 *scale scalar, 4 *bias[col] (svec), 5 +bias[col]+resid
// TA: A stored (K x M) -> A^T @ B.   B stored (K x N).
// OUTB: write bf16 hi/lo outputs; else fp32.   DUAL: second half of N uses B2/bias2.
template<int MODE, bool TA, bool OUTB, bool DUAL>
__global__ __launch_bounds__(256, 2)
void gemm_cp(const bf16* __restrict__ AH, const bf16* __restrict__ AL,
             const bf16* __restrict__ BH, const bf16* __restrict__ BL,
             const bf16* __restrict__ B2H, const bf16* __restrict__ B2L,
             float* __restrict__ Cf, bf16* __restrict__ CH, bf16* __restrict__ CL,
             int K, long lda, long ldb, long ldc,
             long zA, long zB, long zC,
             const float* __restrict__ bias, const float* __restrict__ bias2,
             float scale, const float* __restrict__ resid)
{
    extern __shared__ __align__(128) char smem[];
    const int tid=threadIdx.x, lane=tid&31, warp=tid>>5;
    const int z=blockIdx.z;
    AH += (long)z*zA; AL += (long)z*zA;
    const long co = (long)z*zC;
    const int m0 = blockIdx.y*128, n0 = blockIdx.x*128;
    const uint32_t sb = (uint32_t)__cvta_generic_to_shared(smem);

    const bf16 *bH, *bL; const float* bsel; int nB, bOff;
    if (DUAL && n0 >= 256){ bH=B2H; bL=B2L; bsel=bias2; nB=n0-256; bOff=256; }
    else { bH=BH; bL=BL; bsel=bias; nB=n0; bOff=0; }
    bH += (long)z*zB; bL += (long)z*zB;

    // per-thread cp.async src/dst
    const bf16 *pAH, *pAL;
    uint32_t dA; long stepA;
    if (!TA){
        const int row=tid>>1, k8=tid&1;
        const long o = (long)(m0+row)*lda + k8*8;
        pAH = AH+o; pAL = AL+o;
        dA = (uint32_t)(row*2 + (k8 ^ ((row>>2)&1)))*16;
        stepA = 16;
    } else {
        const int k=tid>>4, m8=tid&15;
        const long o = (long)k*lda + m0 + m8*8;
        pAH = AH+o; pAL = AL+o;
        dA = (uint32_t)(k*16 + (m8 ^ (k&7)))*16;
        stepA = 16*lda;
    }
    const int kb=tid>>4, n8=tid&15;
    const long oB = (long)kb*ldb + nB + n8*8;
    const bf16 *pBH = bH+oB, *pBL = bL+oB;
    const uint32_t dB = (uint32_t)(kb*16 + (n8 ^ (kb&7)))*16;
    const long stepB = 16*ldb;

    // ldsm chunk indices
    const int wm0 = (warp>>1)*32, wn0 = (warp&1)*64;
    const int g = lane>>3;
    int aCh[2];
#pragma unroll
    for (int mt=0; mt<2; mt++){
        if (!TA){
            const int row = wm0 + mt*16 + (lane&7) + (g&1)*8;
            aCh[mt] = row*2 + ((g>>1) ^ ((row>>2)&1));
        } else {
            const int row = (lane&7) + (g>>1)*8;
            const int c = ((wm0 + mt*16)>>3) + (g&1);
            aCh[mt] = row*16 + (c ^ (row&7));
        }
    }
    int bCh[4];
#pragma unroll
    for (int np=0; np<4; np++){
        const int row = (lane&7) + (g&1)*8;
        const int c = ((wn0 + np*16)>>3) + (g>>1);
        bCh[np] = row*16 + (c ^ (row&7));
    }

    float acc[2][8][4];
#pragma unroll
    for (int mt=0;mt<2;mt++)
#pragma unroll
        for (int nt=0;nt<8;nt++)
#pragma unroll
            for (int i=0;i<4;i++) acc[mt][nt][i]=0.f;

    const int NC = K>>4;
#pragma unroll
    for (int c=0; c<3; c++){
        const uint32_t ba = sb + (c&3)*STAGE_B;
        cpa16(ba         + dA, pAH + (long)c*stepA);
        cpa16(ba + 4096  + dA, pAL + (long)c*stepA);
        cpa16(ba + 8192  + dB, pBH + (long)c*stepB);
        cpa16(ba + 12288 + dB, pBL + (long)c*stepB);
        CP_COMMIT();
    }

#pragma unroll 1
    for (int c=0; c<NC; c++){
        CP_WAIT2();
        __syncthreads();
        if (c+3 < NC){
            const uint32_t ba = sb + ((c+3)&3)*STAGE_B;
            cpa16(ba         + dA, pAH + (long)(c+3)*stepA);
            cpa16(ba + 4096  + dA, pAL + (long)(c+3)*stepA);
            cpa16(ba + 8192  + dB, pBH + (long)(c+3)*stepB);
            cpa16(ba + 12288 + dB, pBL + (long)(c+3)*stepB);
        }
        CP_COMMIT();

        const uint32_t ba = sb + (c&3)*STAGE_B;
        uint32_t Ah[2][4], Al[2][4];
#pragma unroll
        for (int mt=0; mt<2; mt++){
            if (!TA){
                ldsm4 (Ah[mt], ba + aCh[mt]*16);
                ldsm4 (Al[mt], ba + 4096 + aCh[mt]*16);
            } else {
                ldsm4t(Ah[mt], ba + aCh[mt]*16);
                ldsm4t(Al[mt], ba + 4096 + aCh[mt]*16);
            }
        }
#pragma unroll
        for (int np=0; np<4; np++){
            uint32_t Bh[4], Bl[4];
            ldsm4t(Bh, ba + 8192  + bCh[np]*16);
            ldsm4t(Bl, ba + 12288 + bCh[np]*16);
            const int n2 = np*2;
#pragma unroll
            for (int mt=0; mt<2; mt++){
                mma_bf16(acc[mt][n2],   Ah[mt], Bh[0], Bh[1]);
                mma_bf16(acc[mt][n2+1], Ah[mt], Bh[2], Bh[3]);
                mma_bf16(acc[mt][n2],   Ah[mt], Bl[0], Bl[1]);
                mma_bf16(acc[mt][n2+1], Ah[mt], Bl[2], Bl[3]);
                mma_bf16(acc[mt][n2],   Al[mt], Bh[0], Bh[1]);
                mma_bf16(acc[mt][n2+1], Al[mt], Bh[2], Bh[3]);
            }
        }
    }

    // epilogue
    const int rbase = m0 + wm0 + (lane>>2);
    const int cbase = n0 + wn0 + (lane&3)*2;
#pragma unroll
    for (int mt=0; mt<2; mt++){
#pragma unroll
        for (int nt=0; nt<8; nt++){
            const int col = cbase + nt*8;
#pragma unroll
            for (int hf=0; hf<2; hf++){
                const int row = rbase + mt*16 + hf*8;
                float v0 = acc[mt][nt][hf*2];
                float v1 = acc[mt][nt][hf*2+1];
                const long gidx = co + (long)row*ldc + col;
                if (MODE==1){ v0 += bsel[col-bOff]; v1 += bsel[col-bOff+1]; }
                if (MODE==2){ v0 *= scale; v1 *= scale; }
                if (MODE==4){ v0 *= bias[col]; v1 *= bias[col+1]; }
                if (MODE==5){
                    const float2 rr = *(const float2*)&resid[gidx];
                    v0 += bias[col]   + rr.x;
                    v1 += bias[col+1] + rr.y;
                }
                if (OUTB){
                    const bf16 h0 = __float2bfloat16_rn(v0);
                    const bf16 h1 = __float2bfloat16_rn(v1);
                    const bf16 l0 = __float2bfloat16_rn(v0 - __bfloat162float(h0));
                    const bf16 l1 = __float2bfloat16_rn(v1 - __bfloat162float(h1));
                    __nv_bfloat162 hp = {h0,h1}, lp = {l0,l1};
                    *(uint32_t*)&CH[gidx] = *(uint32_t*)&hp;
                    *(uint32_t*)&CL[gidx] = *(uint32_t*)&lp;
                } else {
                    *(float2*)&Cf[gidx] = make_float2(v0, v1);
                }
            }
        }
    }
}

__global__ __launch_bounds__(256) void fsplit(const float* __restrict__ x,
                                              bf16* __restrict__ h, bf16* __restrict__ l, int n4){
    const int i = blockIdx.x*256 + threadIdx.x;
    if (i >= n4) return;
    const float4 v = ((const float4*)x)[i];
    const float f[4] = {v.x,v.y,v.z,v.w};
    bf16 hh[4], ll[4];
#pragma unroll
    for (int j=0;j<4;j++){
        hh[j] = __float2bfloat16_rn(f[j]);
        ll[j] = __float2bfloat16_rn(f[j] - __bfloat162float(hh[j]));
    }
    ((uint2*)h)[i] = *(uint2*)hh;
    ((uint2*)l)[i] = *(uint2*)ll;
}

__global__ void reduce8b(const float* __restrict__ part, bf16* __restrict__ oh, bf16* __restrict__ ol){
    const int nper = CI*CI;
    const int i = blockIdx.x*blockDim.x + threadIdx.x;
    if (i >= BATCH*nper) return;
    const int b = i/nper, r = i - b*nper;
    const float* p = part + (long)b*SPLITK*nper + r;
    float s = 0.f;
#pragma unroll
    for (int k=0;k<SPLITK;k++) s += p[(long)k*nper];
    const bf16 h = __float2bfloat16_rn(s);
    oh[i] = h;
    ol[i] = __float2bfloat16_rn(s - __bfloat162float(h));
}

// fold BN into scale/bias vectors
__global__ void prep(const float* gw,const float* betw,const float* mw,const float* vw,const float* bw,
                     const float* gq,const float* betq,const float* mq,const float* vq,const float* bq,
                     float* svw,float* bvw,float* svq,float* bvq){
    const int i = threadIdx.x;  // 512
    const float s = gw[i]*rsqrtf(vw[i]+EPS);
    svw[i] = s; bvw[i] = (bw[i]-mw[i])*s + betw[i];
    const float t = gq[i]*rsqrtf(vq[i]+EPS);
    svq[i] = t; bvq[i] = (bq[i]-mq[i])*t + betq[i];
}

#define SYM(p, s) cudaGetSymbolAddress((void**)&p, s)

extern "C" void kernel_launch(void* const* d_in, const int* in_sizes, int n_in,
                              void* d_out, int out_size){
    (void)in_sizes; (void)n_in; (void)out_size;
    const float* detect=(const float*)d_in[0];
    const float* aim   =(const float*)d_in[1];
    const float* Wg=(const float*)d_in[2];  const float* bg=(const float*)d_in[3];
    const float* Wt=(const float*)d_in[4];  const float* bt=(const float*)d_in[5];
    const float* Wp=(const float*)d_in[6];  const float* bp=(const float*)d_in[7];
    const float* Ww=(const float*)d_in[8];  const float* bw=(const float*)d_in[9];
    const float* gw=(const float*)d_in[10]; const float* betw=(const float*)d_in[11];
    const float* mw=(const float*)d_in[12]; const float* vw=(const float*)d_in[13];
    const float* Wq=(const float*)d_in[14]; const float* bq=(const float*)d_in[15];
    const float* gq=(const float*)d_in[16]; const float* betq=(const float*)d_in[17];
    const float* mq=(const float*)d_in[18]; const float* vq=(const float*)d_in[19];

    float* out    = (float*)d_out;
    float* out_na = out;
    float* out_nd = out + (long)RA*C;

    bf16 *detH,*detL,*aimH,*aimL,*WgH,*WgL,*WtH,*WtL,*WpH,*WpL,*WwH,*WwL,*WqH,*WqL;
    bf16 *dpH,*dpL,*atH,*atL,*m1H,*m1L,*m2H,*m2L,*m1sH,*m1sL,*m2sH,*m2sL;
    float *p1,*p2,*svw,*bvw,*svq,*bvq;
    SYM(detH,g_detH); SYM(detL,g_detL); SYM(aimH,g_aimH); SYM(aimL,g_aimL);
    SYM(WgH,g_WgH); SYM(WgL,g_WgL); SYM(WtH,g_WtH); SYM(WtL,g_WtL);
    SYM(WpH,g_WpH); SYM(WpL,g_WpL); SYM(WwH,g_WwH); SYM(WwL,g_WwL);
    SYM(WqH,g_WqH); SYM(WqL,g_WqL);
    SYM(dpH,g_dpH); SYM(dpL,g_dpL); SYM(atH,g_atH); SYM(atL,g_atL);
    SYM(m1H,g_m1H); SYM(m1L,g_m1L); SYM(m2H,g_m2H); SYM(m2L,g_m2L);
    SYM(m1sH,g_m1sH); SYM(m1sL,g_m1sL); SYM(m2sH,g_m2sH); SYM(m2sL,g_m2sL);
    SYM(p1,g_p1); SYM(p2,g_p2);
    SYM(svw,g_svw); SYM(bvw,g_bvw); SYM(svq,g_svq); SYM(bvq,g_bvq);

    cudaFuncSetAttribute(gemm_cp<1,false,true ,true >, cudaFuncAttributeMaxDynamicSharedMemorySize, SMEM_BYTES);
    cudaFuncSetAttribute(gemm_cp<2,true ,false,false>, cudaFuncAttributeMaxDynamicSharedMemorySize, SMEM_BYTES);
    cudaFuncSetAttribute(gemm_cp<4,false,true ,false>, cudaFuncAttributeMaxDynamicSharedMemorySize, SMEM_BYTES);
    cudaFuncSetAttribute(gemm_cp<5,false,false,false>, cudaFuncAttributeMaxDynamicSharedMemorySize, SMEM_BYTES);

    const dim3 blk(256);
    const long sM = (long)CI*CI;

    // launches 1-4, so launch #5 (the big fused projection) is the ncu capture target
    fsplit<<<(RD*C/4+255)/256, 256>>>(detect, detH, detL, RD*C/4);
    fsplit<<<(C*CI/4+255)/256, 256>>>(Wg, WgH, WgL, C*CI/4);
    fsplit<<<(C*CI/4+255)/256, 256>>>(Wp, WpH, WpL, C*CI/4);
    prep<<<1,512>>>(gw,betw,mw,vw,bw, gq,betq,mq,vq,bq, svw,bvw,svq,bvq);

    // fused detect projection: [dx|ph] = detect @ [Wg|Wp] + [bg|bp]
    gemm_cp<1,false,true,true><<<dim3(4,RD/128,1),blk,SMEM_BYTES>>>(
        detH,detL, WgH,WgL, WpH,WpL, nullptr,dpH,dpL,
        C, C,CI,512, 0,0,0, bg,bp, 0.f, nullptr);

    fsplit<<<(RA*C/4+255)/256, 256>>>(aim, aimH, aimL, RA*C/4);
    fsplit<<<(C*CI/4+255)/256, 256>>>(Wt, WtH, WtL, C*CI/4);

    // fused aim projection: [ax|th] = aim @ [Wg|Wt] + [bg|bt]
    gemm_cp<1,false,true,true><<<dim3(4,RA/128,1),blk,SMEM_BYTES>>>(
        aimH,aimL, WgH,WgL, WtH,WtL, nullptr,atH,atL,
        C, C,CI,512, 0,0,0, bg,bt, 0.f, nullptr);

    fsplit<<<(CI*C/4+255)/256, 256>>>(Ww, WwH, WwL, CI*C/4);
    fsplit<<<(CI*C/4+255)/256, 256>>>(Wq, WqH, WqL, CI*C/4);

    // gram: m1 = ph^T dx / ND ; m2 = th^T ax / NA   (split-K x8, fp32 partials)
    gemm_cp<2,true,false,false><<<dim3(2,2,BATCH*SPLITK),blk,SMEM_BYTES>>>(
        dpH+256,dpL+256, dpH,dpL, nullptr,nullptr, p1,nullptr,nullptr,
        ND/SPLITK, 512,512,CI, (long)(ND/SPLITK)*512,(long)(ND/SPLITK)*512,sM,
        nullptr,nullptr, 1.f/(float)ND, nullptr);
    gemm_cp<2,true,false,false><<<dim3(2,2,BATCH*SPLITK),blk,SMEM_BYTES>>>(
        atH+256,atL+256, atH,atL, nullptr,nullptr, p2,nullptr,nullptr,
        NA/SPLITK, 512,512,CI, (long)(NA/SPLITK)*512,(long)(NA/SPLITK)*512,sM,
        nullptr,nullptr, 1.f/(float)NA, nullptr);
    {
        const int n = BATCH*CI*CI;
        reduce8b<<<(n+255)/256,256>>>(p1, m1H, m1L);
        reduce8b<<<(n+255)/256,256>>>(p2, m2H, m2L);
    }

    // fold: m1s = (m1 @ Ww) * svw ; m2s = (m2 @ Wq) * svq   (tiny per-batch GEMMs)
    gemm_cp<4,false,true,false><<<dim3(4,2,BATCH),blk,SMEM_BYTES>>>(
        m1H,m1L, WwH,WwL, nullptr,nullptr, nullptr,m1sH,m1sL,
        CI, CI,C,C, sM,0,(long)CI*C, svw,nullptr, 0.f, nullptr);
    gemm_cp<4,false,true,false><<<dim3(4,2,BATCH),blk,SMEM_BYTES>>>(
        m2H,m2L, WqH,WqL, nullptr,nullptr, nullptr,m2sH,m2sL,
        CI, CI,C,C, sM,0,(long)CI*C, svq,nullptr, 0.f, nullptr);

    // outputs: out_na = th @ m1s + bvw + aim ; out_nd = ph @ m2s + bvq + detect
    gemm_cp<5,false,false,false><<<dim3(4,NA/128,BATCH),blk,SMEM_BYTES>>>(
        atH+256,atL+256, m1sH,m1sL, nullptr,nullptr, out_na,nullptr,nullptr,
        CI, 512,C,C, (long)NA*512,(long)CI*C,(long)NA*C,
        bvw,nullptr, 0.f, aim);
    gemm_cp<5,false,false,false><<<dim3(4,ND/128,BATCH),blk,SMEM_BYTES>>>(
        dpH+256,dpL+256, m2sH,m2sL, nullptr,nullptr, out_nd,nullptr,nullptr,
        CI, 512,C,C, (long)ND*512,(long)CI*C,(long)ND*C,
        bvq,nullptr, 0.f, detect);
}